// round 14
// baseline (speedup 1.0000x reference)
#include <cuda_runtime.h>
#include <cuda_bf16.h>
#include <math.h>
#include <string.h>
#include <stdint.h>

// Problem constants
#define H_   16
#define D_   128
#define DM   2048   // H_*D_
#define NB   1024   // N_BASIS
#define MEM  512    // memory length (l)
#define QL   2048   // query length
#define NPOS 1024   // 2*l sample positions
#define BW   192    // half-bandwidth of F F^T + ridge

// generic mma GEMM tiling (BK=32, row stride 40 bf16 = 80B, conflict-free)
#define GBK 32
#define GST 40
#define GTILE_B (128 * GST * 2)          // 10240 bytes per tile
#define STAGE_B (4 * GTILE_B)            // 40960
#define GSMEM_B (3 * STAGE_B)            // 122880

// ctx kernel tiling: A(r) stride 40; V tiles stride 24; BK=16
#define RT_STRIDE 40
#define RT_B (128 * RT_STRIDE * 2)       // 10240
#define VSTRIDE 24
#define VT_B (128 * VSTRIDE * 2)         // 6144
#define CSTAGE_B (2 * RT_B + 2 * VT_B)   // 32768
#define CSMEM_B (3 * CSTAGE_B)           // 98304

// ----------------------------------------------------------------------------
// Device scratch (static globals -- no allocation anywhere)
// ----------------------------------------------------------------------------
__device__ float g_km[DM];
__device__ float g_ks[DM];
__device__ float g_gw[2][MEM];
__device__ float g_pb[2][4][DM];
__device__ float g_bvmu[DM];
__device__ float g_bvsg[DM];
__device__ float g_mu[H_ * QL];
__device__ float g_amp[2][H_ * QL];
__device__ float g_c2[2][H_ * QL];
__device__ float g_bmu[NB];

// bf16 split operands
__device__ __nv_bfloat16 g_GTh[NB * MEM], g_GTl[NB * MEM];   // G^T [n][l] (host)
__device__ __nv_bfloat16 g_kh[MEM * DM],  g_kl[MEM * DM];    // k [l][e]
__device__ __nv_bfloat16 g_Wvh[DM * DM],  g_Wvl[DM * DM];
__device__ __nv_bfloat16 g_Woh[DM * DM],  g_Wol[DM * DM];
__device__ __nv_bfloat16 g_Pvh[DM * MEM], g_Pvl[DM * MEM];   // Pv^T [hd][l]
__device__ __nv_bfloat16 g_Vh[DM * NB],   g_Vl[DM * NB];     // V^T [hd][n]
__device__ __nv_bfloat16 g_Ch[QL * DM],   g_Cl[QL * DM];     // ctx [q][hd]

// ----------------------------------------------------------------------------
// Host-side constant: G = solve(F F^T + 0.5 I, F)^T [256:768], emitted as
// G^T bf16 hi/lo (pure function of compile-time constants).
// ----------------------------------------------------------------------------
static double hF[NB][NPOS];
static double hA[NB][NB];
static float    hostbmu[NB];
static uint16_t hostGTh[NB * MEM], hostGTl[NB * MEM];

static inline uint16_t f2bf(float x) {
    uint32_t u; memcpy(&u, &x, 4);
    uint32_t r = (u + 0x7FFFu + ((u >> 16) & 1u)) >> 16;
    return (uint16_t)r;
}
static inline float bf2f(uint16_t h) {
    uint32_t u = (uint32_t)h << 16; float f; memcpy(&f, &u, 4); return f;
}

static void compute_G_host() {
    static double mu[NB], sgv[NB], pos[NPOS];
    static int plo[NB], phi[NB];
    const double SQ2PI = 2.506628274631000502;

    for (int i = 0; i < NB; i++) {
        mu[i]  = (double)(i >> 1) / 511.0;
        sgv[i] = (i & 1) ? 0.01 : 0.005;
        hostbmu[i] = (float)mu[i];
    }
    double a = -0.5 + 1.0 / 1024.0;
    double b =  1.5 - 1.0 / 1024.0;
    double step = (b - a) / 1023.0;
    for (int p = 0; p < NPOS; p++) pos[p] = a + p * step;

    for (int i = 0; i < NB; i++) {
        int lo = NPOS, hi = -1;
        double inv = 1.0 / sgv[i];
        double amp = inv / SQ2PI;
        for (int p = 0; p < NPOS; p++) {
            double t = (pos[p] - mu[i]) * inv;
            if (t > -15.0 && t < 15.0) {
                hF[i][p] = exp(-0.5 * t * t) * amp;
                if (p < lo) lo = p;
                hi = p;
            } else hF[i][p] = 0.0;
        }
        plo[i] = lo; phi[i] = hi;
    }

    memset(hA, 0, sizeof(hA));
    for (int i = 0; i < NB; i++) {
        int jmax = (i + BW < NB) ? i + BW : NB - 1;
        for (int j = i; j <= jmax; j++) {
            int lo = plo[i] > plo[j] ? plo[i] : plo[j];
            int hi = phi[i] < phi[j] ? phi[i] : phi[j];
            double s = 0.0;
            for (int p = lo; p <= hi; p++) s += hF[i][p] * hF[j][p];
            hA[i][j] = s; hA[j][i] = s;
        }
        hA[i][i] += 0.5;
    }

    for (int j = 0; j < NB; j++) {
        int kmin = (j - BW > 0) ? j - BW : 0;
        double s = hA[j][j];
        for (int k = kmin; k < j; k++) s -= hA[j][k] * hA[j][k];
        double Ljj = sqrt(s);
        hA[j][j] = Ljj;
        double invL = 1.0 / Ljj;
        int imax = (j + BW < NB) ? j + BW : NB - 1;
        for (int i = j + 1; i <= imax; i++) {
            int k0 = (i - BW > kmin) ? i - BW : kmin;
            double t = hA[i][j];
            for (int k = k0; k < j; k++) t -= hA[i][k] * hA[j][k];
            hA[i][j] = t * invL;
        }
    }

    static double yv[NB], xv[NB];
    for (int p = 256; p < 768; p++) {
        for (int i = 0; i < NB; i++) {
            int k0 = (i - BW > 0) ? i - BW : 0;
            double s = hF[i][p];
            for (int k = k0; k < i; k++) s -= hA[i][k] * yv[k];
            yv[i] = s / hA[i][i];
        }
        for (int i = NB - 1; i >= 0; i--) {
            int k1 = (i + BW < NB) ? i + BW : NB - 1;
            double s = yv[i];
            for (int k = i + 1; k <= k1; k++) s -= hA[k][i] * xv[k];
            xv[i] = s / hA[i][i];
        }
        int l = p - 256;
        for (int n = 0; n < NB; n++) {
            float g = (float)xv[n];
            uint16_t h = f2bf(g);
            hostGTh[n * MEM + l] = h;
            hostGTl[n * MEM + l] = f2bf(g - bf2f(h));
        }
    }
}

// ----------------------------------------------------------------------------
// PTX helpers (sm_80-portable: ldmatrix / mma.sync / cp.async)
// ----------------------------------------------------------------------------
__device__ __forceinline__ uint32_t smem_u32(const void* p) {
    uint32_t a;
    asm("{ .reg .u64 t; cvta.to.shared.u64 t, %1; cvt.u32.u64 %0, t; }" : "=r"(a) : "l"(p));
    return a;
}
__device__ __forceinline__ void cpa16(uint32_t s, const void* g) {
    asm volatile("cp.async.cg.shared.global [%0], [%1], 16;" :: "r"(s), "l"(g));
}
#define CP_COMMIT() asm volatile("cp.async.commit_group;" ::: "memory")
#define CP_WAIT1()  asm volatile("cp.async.wait_group 1;" ::: "memory")
#define LDSM4(r0, r1, r2, r3, addr) \
    asm volatile("ldmatrix.sync.aligned.m8n8.x4.shared.b16 {%0,%1,%2,%3}, [%4];" \
                 : "=r"(r0), "=r"(r1), "=r"(r2), "=r"(r3) : "r"(addr))
#define MMA16816(c, a, b) \
    asm volatile("mma.sync.aligned.m16n8k16.row.col.f32.bf16.bf16.f32 " \
                 "{%0,%1,%2,%3}, {%4,%5,%6,%7}, {%8,%9}, {%0,%1,%2,%3};" \
                 : "+f"((c)[0]), "+f"((c)[1]), "+f"((c)[2]), "+f"((c)[3]) \
                 : "r"((a)[0]), "r"((a)[1]), "r"((a)[2]), "r"((a)[3]), \
                   "r"((b)[0]), "r"((b)[1]))

__device__ __forceinline__ uint32_t pack_bf2(float a, float b) {
    __nv_bfloat162 t = __halves2bfloat162(__float2bfloat16(a), __float2bfloat16(b));
    uint32_t u; memcpy(&u, &t, 4); return u;
}

// ----------------------------------------------------------------------------
// Tensor-core NT GEMM with bf16 split operands, BK=32, 3-stage cp.async:
// out[m][n] = scale * sum_k (Ahi+Alo)[m][k] * (Bhi+Blo)[n][k]  (lo*lo dropped)
// Epilogue writes optional fp32 C and/or bf16 hi/lo split C.
// ----------------------------------------------------------------------------
__global__ __launch_bounds__(256) void gemm_mma_nt(
    const __nv_bfloat16* __restrict__ Ahi, const __nv_bfloat16* __restrict__ Alo,
    const __nv_bfloat16* __restrict__ Bhi, const __nv_bfloat16* __restrict__ Blo,
    float* __restrict__ Cf, __nv_bfloat16* __restrict__ Ch,
    __nv_bfloat16* __restrict__ Cl, int ldc, int K, float scale)
{
    extern __shared__ char smraw[];
    uint32_t base = smem_u32(smraw);

    int tid = threadIdx.x, lane = tid & 31, wid = tid >> 5;
    int m0 = blockIdx.x * 128, n0 = blockIdx.y * 128;
    int wm = (wid & 3) << 5;
    int wn = (wid >> 2) << 6;

    float acc[2][8][4];
#pragma unroll
    for (int i = 0; i < 2; i++)
#pragma unroll
        for (int j = 0; j < 8; j++)
#pragma unroll
            for (int l = 0; l < 4; l++) acc[i][j][l] = 0.f;

    // cp.async mapping: thread -> row r = tid>>1, 16B chunk pair cbase = (tid&1)*2
    int r = tid >> 1, cb = (tid & 1) * 2;
    const __nv_bfloat16* gA0 = Ahi + (size_t)(m0 + r) * K + cb * 8;
    const __nv_bfloat16* gA1 = Alo + (size_t)(m0 + r) * K + cb * 8;
    const __nv_bfloat16* gB0 = Bhi + (size_t)(n0 + r) * K + cb * 8;
    const __nv_bfloat16* gB1 = Blo + (size_t)(n0 + r) * K + cb * 8;
    uint32_t soff = (uint32_t)(r * GST + cb * 8) * 2;

    const int NT = K / GBK;

#pragma unroll
    for (int p = 0; p < 2; p++) {
        uint32_t sb = base + p * STAGE_B + soff;
        int k0 = p * GBK;
        cpa16(sb,                    gA0 + k0);
        cpa16(sb + 16,               gA0 + k0 + 8);
        cpa16(sb + GTILE_B,          gA1 + k0);
        cpa16(sb + GTILE_B + 16,     gA1 + k0 + 8);
        cpa16(sb + 2 * GTILE_B,      gB0 + k0);
        cpa16(sb + 2 * GTILE_B + 16, gB0 + k0 + 8);
        cpa16(sb + 3 * GTILE_B,      gB1 + k0);
        cpa16(sb + 3 * GTILE_B + 16, gB1 + k0 + 8);
        CP_COMMIT();
    }

    uint32_t a_off = ((uint32_t)((lane & 15)) * GST + ((lane >> 4) << 3)) * 2;
    uint32_t b_off = ((uint32_t)((lane & 7) + ((lane & 16) ? 8 : 0)) * GST +
                     ((lane & 8) ? 8 : 0)) * 2;

    int s = 0;
    for (int it = 0; it < NT; it++) {
        CP_WAIT1();
        __syncthreads();

        if (it + 2 < NT) {
            int s2 = s + 2; if (s2 >= 3) s2 -= 3;
            uint32_t sb = base + s2 * STAGE_B + soff;
            int k0 = (it + 2) * GBK;
            cpa16(sb,                    gA0 + k0);
            cpa16(sb + 16,               gA0 + k0 + 8);
            cpa16(sb + GTILE_B,          gA1 + k0);
            cpa16(sb + GTILE_B + 16,     gA1 + k0 + 8);
            cpa16(sb + 2 * GTILE_B,      gB0 + k0);
            cpa16(sb + 2 * GTILE_B + 16, gB0 + k0 + 8);
            cpa16(sb + 3 * GTILE_B,      gB1 + k0);
            cpa16(sb + 3 * GTILE_B + 16, gB1 + k0 + 8);
        }
        CP_COMMIT();

        uint32_t tb = base + s * STAGE_B;

#pragma unroll
        for (int kk2 = 0; kk2 < 2; kk2++) {
            uint32_t ko = kk2 * 32;   // 16 bf16 = 32 bytes

            uint32_t ah[2][4], al[2][4];
            {
                uint32_t ad = tb + (uint32_t)wm * GST * 2 + a_off + ko;
                LDSM4(ah[0][0], ah[0][1], ah[0][2], ah[0][3], ad);
                LDSM4(ah[1][0], ah[1][1], ah[1][2], ah[1][3], ad + 16 * GST * 2);
                uint32_t adl = ad + GTILE_B;
                LDSM4(al[0][0], al[0][1], al[0][2], al[0][3], adl);
                LDSM4(al[1][0], al[1][1], al[1][2], al[1][3], adl + 16 * GST * 2);
            }
            uint32_t bh[8][2], bl[8][2];
            {
                uint32_t bd = tb + 2 * GTILE_B + (uint32_t)wn * GST * 2 + b_off + ko;
#pragma unroll
                for (int j = 0; j < 4; j++) {
                    uint32_t ad = bd + (uint32_t)j * 16 * GST * 2;
                    LDSM4(bh[2 * j][0], bh[2 * j][1], bh[2 * j + 1][0], bh[2 * j + 1][1], ad);
                    LDSM4(bl[2 * j][0], bl[2 * j][1], bl[2 * j + 1][0], bl[2 * j + 1][1],
                          ad + GTILE_B);
                }
            }

#pragma unroll
            for (int mt = 0; mt < 2; mt++)
#pragma unroll
                for (int nt = 0; nt < 8; nt++) {
                    MMA16816(acc[mt][nt], ah[mt], bh[nt]);
                    MMA16816(acc[mt][nt], ah[mt], bl[nt]);
                    MMA16816(acc[mt][nt], al[mt], bh[nt]);
                }
        }
        s++; if (s >= 3) s -= 3;
    }

    // epilogue
    int erow = lane >> 2;
    int ecol = (lane & 3) << 1;
#pragma unroll
    for (int mt = 0; mt < 2; mt++)
#pragma unroll
        for (int nt = 0; nt < 8; nt++) {
            int row = m0 + wm + mt * 16 + erow;
            int col = n0 + wn + nt * 8 + ecol;
            float v00 = acc[mt][nt][0] * scale, v01 = acc[mt][nt][1] * scale;
            float v10 = acc[mt][nt][2] * scale, v11 = acc[mt][nt][3] * scale;
            size_t i0 = (size_t)row * ldc + col;
            size_t i1 = (size_t)(row + 8) * ldc + col;
            if (Cf) {
                *(float2*)&Cf[i0] = make_float2(v00, v01);
                *(float2*)&Cf[i1] = make_float2(v10, v11);
            }
            if (Ch) {
                __nv_bfloat16 h00 = __float2bfloat16(v00), h01 = __float2bfloat16(v01);
                __nv_bfloat16 h10 = __float2bfloat16(v10), h11 = __float2bfloat16(v11);
                *(__nv_bfloat162*)&Ch[i0] = __halves2bfloat162(h00, h01);
                *(__nv_bfloat162*)&Ch[i1] = __halves2bfloat162(h10, h11);
                *(__nv_bfloat162*)&Cl[i0] = __halves2bfloat162(
                    __float2bfloat16(v00 - __bfloat162float(h00)),
                    __float2bfloat16(v01 - __bfloat162float(h01)));
                *(__nv_bfloat162*)&Cl[i1] = __halves2bfloat162(
                    __float2bfloat16(v10 - __bfloat162float(h10)),
                    __float2bfloat16(v11 - __bfloat162float(h11)));
            }
        }
}

// ----------------------------------------------------------------------------
// fast exp2 on the FMA pipe (x <= 0), no MUFU.
// ----------------------------------------------------------------------------
__device__ __forceinline__ float fast_exp2(float x) {
    x = fmaxf(x, -126.0f);
    float fl = floorf(x);
    float f = x - fl;
    float p =        1.8775767e-3f;
    p = fmaf(p, f,   8.9893397e-3f);
    p = fmaf(p, f,   5.5826318e-2f);
    p = fmaf(p, f,   2.4015361e-1f);
    p = fmaf(p, f,   6.9315308e-1f);
    p = fmaf(p, f,   9.9999994e-1f);
    int e = __float2int_rn(fl);
    float s = __int_as_float((e + 127) << 23);
    return p * s;
}

// ----------------------------------------------------------------------------
// Fused ctx kernel on tensor cores (BK=16). Grid (q tiles = 16, heads = 16).
// ctx[q][h*128+d] = sum_n r(h,q,n) * V^T[h*128+d][n]
// Stage layout: [Rh(10240) | Rl(10240) | Vh(6144) | Vl(6144)]
// ----------------------------------------------------------------------------
__global__ __launch_bounds__(256) void ctx_mma() {
    extern __shared__ char smraw[];
    uint32_t base = smem_u32(smraw);
    char* smp = smraw;

    int tid = threadIdx.x, lane = tid & 31, wid = tid >> 5;
    int q0 = blockIdx.x * 128;
    int h  = blockIdx.y;
    int wm = (wid & 3) << 5;
    int wn = (wid >> 2) << 6;

    float acc[2][8][4];
#pragma unroll
    for (int i = 0; i < 2; i++)
#pragma unroll
        for (int j = 0; j < 8; j++)
#pragma unroll
            for (int l = 0; l < 4; l++) acc[i][j][l] = 0.f;

    int vrow = tid >> 1, hf = tid & 1;
    const __nv_bfloat16* gV0 = g_Vh + (size_t)(h * 128 + vrow) * NB + hf * 8;
    const __nv_bfloat16* gV1 = g_Vl + (size_t)(h * 128 + vrow) * NB + hf * 8;
    uint32_t vsoff = (uint32_t)(vrow * VSTRIDE + hf * 8) * 2;

    int rq = tid & 127;
    int ng = tid >> 7;
    float mu_q, a0_q, a1_q, c0_q, c1_q;
    {
        int row = h * QL + q0 + rq;
        mu_q = g_mu[row];
        a0_q = g_amp[0][row]; a1_q = g_amp[1][row];
        c0_q = g_c2[0][row];  c1_q = g_c2[1][row];
    }
    uint32_t rsoff = (uint32_t)(rq * RT_STRIDE + ng * 8) * 2;

#pragma unroll
    for (int p = 0; p < 2; p++) {
        uint32_t sb = base + p * CSTAGE_B + 2 * RT_B + vsoff;
        cpa16(sb,        gV0 + p * 16);
        cpa16(sb + VT_B, gV1 + p * 16);
        CP_COMMIT();
    }

    uint32_t a_off = ((uint32_t)((lane & 15)) * RT_STRIDE + ((lane >> 4) << 3)) * 2;
    uint32_t b_off = ((uint32_t)((lane & 7) + ((lane & 16) ? 8 : 0)) * VSTRIDE +
                     ((lane & 8) ? 8 : 0)) * 2;

    const int NT = NB / 16;   // 64
    int s = 0;
    for (int it = 0; it < NT; it++) {
        CP_WAIT1();
        __syncthreads();

        if (it + 2 < NT) {
            int s2 = s + 2; if (s2 >= 3) s2 -= 3;
            uint32_t sb = base + s2 * CSTAGE_B + 2 * RT_B + vsoff;
            cpa16(sb,        gV0 + (it + 2) * 16);
            cpa16(sb + VT_B, gV1 + (it + 2) * 16);
        }
        CP_COMMIT();

        {
            int nb8 = it * 16 + ng * 8;
            uint32_t ph[4], pl[4];
#pragma unroll
            for (int jj = 0; jj < 4; jj++) {
                float bm0 = g_bmu[nb8 + 2 * jj];
                float bm1 = g_bmu[nb8 + 2 * jj + 1];
                float dx0 = bm0 - mu_q, dx1 = bm1 - mu_q;
                float r0 = a0_q * fast_exp2(c0_q * dx0 * dx0);
                float r1 = a1_q * fast_exp2(c1_q * dx1 * dx1);
                __nv_bfloat16 h0 = __float2bfloat16(r0);
                __nv_bfloat16 h1 = __float2bfloat16(r1);
                ph[jj] = pack_bf2(r0, r1);
                pl[jj] = pack_bf2(r0 - __bfloat162float(h0),
                                  r1 - __bfloat162float(h1));
            }
            char* dst = smp + s * CSTAGE_B + rsoff;
            *(uint4*)dst          = make_uint4(ph[0], ph[1], ph[2], ph[3]);
            *(uint4*)(dst + RT_B) = make_uint4(pl[0], pl[1], pl[2], pl[3]);
        }
        __syncthreads();

        uint32_t tb = base + s * CSTAGE_B;

        uint32_t ah[2][4], al[2][4];
        {
            uint32_t ad = tb + (uint32_t)wm * RT_STRIDE * 2 + a_off;
            LDSM4(ah[0][0], ah[0][1], ah[0][2], ah[0][3], ad);
            LDSM4(ah[1][0], ah[1][1], ah[1][2], ah[1][3], ad + 16 * RT_STRIDE * 2);
            uint32_t adl = ad + RT_B;
            LDSM4(al[0][0], al[0][1], al[0][2], al[0][3], adl);
            LDSM4(al[1][0], al[1][1], al[1][2], al[1][3], adl + 16 * RT_STRIDE * 2);
        }
        uint32_t bh[8][2], bl[8][2];
        {
            uint32_t bd = tb + 2 * RT_B + (uint32_t)wn * VSTRIDE * 2 + b_off;
#pragma unroll
            for (int j = 0; j < 4; j++) {
                uint32_t ad = bd + (uint32_t)j * 16 * VSTRIDE * 2;
                LDSM4(bh[2 * j][0], bh[2 * j][1], bh[2 * j + 1][0], bh[2 * j + 1][1], ad);
                LDSM4(bl[2 * j][0], bl[2 * j][1], bl[2 * j + 1][0], bl[2 * j + 1][1],
                      ad + VT_B);
            }
        }

#pragma unroll
        for (int mt = 0; mt < 2; mt++)
#pragma unroll
            for (int nt = 0; nt < 8; nt++) {
                MMA16816(acc[mt][nt], ah[mt], bh[nt]);
                MMA16816(acc[mt][nt], ah[mt], bl[nt]);
                MMA16816(acc[mt][nt], al[mt], bh[nt]);
            }
        s++; if (s >= 3) s -= 3;
    }

    int erow = lane >> 2;
    int ecol = (lane & 3) << 1;
#pragma unroll
    for (int mt = 0; mt < 2; mt++)
#pragma unroll
        for (int nt = 0; nt < 8; nt++) {
            int row = q0 + wm + mt * 16 + erow;
            int col = h * 128 + wn + nt * 8 + ecol;
            float v00 = acc[mt][nt][0], v01 = acc[mt][nt][1];
            float v10 = acc[mt][nt][2], v11 = acc[mt][nt][3];
            size_t i0 = (size_t)row * DM + col;
            size_t i1 = (size_t)(row + 8) * DM + col;
            __nv_bfloat16 h00 = __float2bfloat16(v00), h01 = __float2bfloat16(v01);
            __nv_bfloat16 h10 = __float2bfloat16(v10), h11 = __float2bfloat16(v11);
            *(__nv_bfloat162*)&g_Ch[i0] = __halves2bfloat162(h00, h01);
            *(__nv_bfloat162*)&g_Ch[i1] = __halves2bfloat162(h10, h11);
            *(__nv_bfloat162*)&g_Cl[i0] = __halves2bfloat162(
                __float2bfloat16(v00 - __bfloat162float(h00)),
                __float2bfloat16(v01 - __bfloat162float(h01)));
            *(__nv_bfloat162*)&g_Cl[i1] = __halves2bfloat162(
                __float2bfloat16(v10 - __bfloat162float(h10)),
                __float2bfloat16(v11 - __bfloat162float(h11)));
        }
}

// ----------------------------------------------------------------------------
// split fp32 -> bf16 hi/lo
// ----------------------------------------------------------------------------
__global__ __launch_bounds__(256) void split_kernel(
    const float4* __restrict__ src, __nv_bfloat162* __restrict__ hi,
    __nv_bfloat162* __restrict__ lo, int n4)
{
    int i = blockIdx.x * 256 + threadIdx.x;
    if (i >= n4) return;
    float4 v = src[i];
    __nv_bfloat16 h0 = __float2bfloat16(v.x);
    __nv_bfloat16 h1 = __float2bfloat16(v.y);
    __nv_bfloat16 h2 = __float2bfloat16(v.z);
    __nv_bfloat16 h3 = __float2bfloat16(v.w);
    hi[2 * i]     = __halves2bfloat162(h0, h1);
    hi[2 * i + 1] = __halves2bfloat162(h2, h3);
    lo[2 * i]     = __halves2bfloat162(
        __float2bfloat16(v.x - __bfloat162float(h0)),
        __float2bfloat16(v.y - __bfloat162float(h1)));
    lo[2 * i + 1] = __halves2bfloat162(
        __float2bfloat16(v.z - __bfloat162float(h2)),
        __float2bfloat16(v.w - __bfloat162float(h3)));
}

// ----------------------------------------------------------------------------
// gw[l] = sum_n (GTh+GTl)[n][l] * w[n]   (both wmu and wsig)
// ----------------------------------------------------------------------------
__global__ __launch_bounds__(128) void gw_kernel(
    const float* __restrict__ wmu, const float* __restrict__ wsig)
{
    int l = blockIdx.x * 128 + threadIdx.x;
    float sm = 0.f, ss = 0.f;
    for (int n = 0; n < NB; n++) {
        float g = __bfloat162float(g_GTh[n * MEM + l]) +
                  __bfloat162float(g_GTl[n * MEM + l]);
        sm += g * wmu[n];
        ss += g * wsig[n];
    }
    g_gw[0][l] = sm;
    g_gw[1][l] = ss;
}

// ----------------------------------------------------------------------------
// bv[e] = sum_l gw[l] * k[l][e]  (fp32 k), two-stage over 4 l-chunks
// ----------------------------------------------------------------------------
__global__ __launch_bounds__(256) void bv_part(const float* __restrict__ kin) {
    int e = blockIdx.x * 256 + threadIdx.x;
    int c = blockIdx.y;
    float sm = 0.f, ss = 0.f;
    int lbeg = c * 128;
    for (int l = lbeg; l < lbeg + 128; l++) {
        float kv = kin[(size_t)l * DM + e];
        sm += kv * g_gw[0][l];
        ss += kv * g_gw[1][l];
    }
    g_pb[0][c][e] = sm;
    g_pb[1][c][e] = ss;
}

__global__ __launch_bounds__(256) void bv_reduce() {
    int e = blockIdx.x * 256 + threadIdx.x;
    float a = 0.f, b = 0.f;
#pragma unroll
    for (int c = 0; c < 4; c++) { a += g_pb[0][c][e]; b += g_pb[1][c][e]; }
    g_bvmu[e] = a;
    g_bvsg[e] = b;
}

// ----------------------------------------------------------------------------
// km[i] = (Wk[i,:].bv_mu)/sqrt(D), ks likewise
// ----------------------------------------------------------------------------
__global__ __launch_bounds__(256) void kmdot_kernel(const float* __restrict__ Wk) {
    int warp = threadIdx.x >> 5, lane = threadIdx.x & 31;
    int row = blockIdx.x * 8 + warp;
    const float4* w4 = (const float4*)(Wk + (size_t)row * DM);
    const float4* m4 = (const float4*)g_bvmu;
    const float4* s4 = (const float4*)g_bvsg;
    float xm = 0.f, xs = 0.f;
#pragma unroll
    for (int it = 0; it < 16; it++) {
        int idx = it * 32 + lane;
        float4 w = w4[idx], m = m4[idx], sv = s4[idx];
        xm += w.x * m.x + w.y * m.y + w.z * m.z + w.w * m.w;
        xs += w.x * sv.x + w.y * sv.y + w.z * sv.z + w.w * sv.w;
    }
#pragma unroll
    for (int o = 16; o > 0; o >>= 1) {
        xm += __shfl_xor_sync(0xffffffffu, xm, o);
        xs += __shfl_xor_sync(0xffffffffu, xs, o);
    }
    if (lane == 0) {
        const float inv_sqrt_d = 0.08838834764831843f;
        g_km[row] = xm * inv_sqrt_d;
        g_ks[row] = xs * inv_sqrt_d;
    }
}

// ----------------------------------------------------------------------------
// per (h,q): mu = sigmoid(q.km); sg = max(softplus(q.ks), 1e-4);
// hoisted per-parity Gaussian params amp_p, c_p.
// ----------------------------------------------------------------------------
__global__ __launch_bounds__(256) void musig_kernel(const float* __restrict__ q) {
    int warp = threadIdx.x >> 5, lane = threadIdx.x & 31;
    int row = blockIdx.x * 8 + warp;
    int h = row >> 11;
    float4 qv = reinterpret_cast<const float4*>(q + (size_t)row * D_)[lane];
    float4 km = reinterpret_cast<const float4*>(g_km + h * D_)[lane];
    float4 ks = reinterpret_cast<const float4*>(g_ks + h * D_)[lane];
    float xm = qv.x * km.x + qv.y * km.y + qv.z * km.z + qv.w * km.w;
    float xs = qv.x * ks.x + qv.y * ks.y + qv.z * ks.z + qv.w * ks.w;
#pragma unroll
    for (int o = 16; o > 0; o >>= 1) {
        xm += __shfl_xor_sync(0xffffffffu, xm, o);
        xs += __shfl_xor_sync(0xffffffffu, xs, o);
    }
    if (lane == 0) {
        const float INV_SQRT_2PI = 0.3989422804014327f;
        const float NHALF_LOG2E  = -0.7213475204444817f;
        float m_ = 1.f / (1.f + expf(-xm));
        float sp = fmaxf(xs, 0.f) + log1pf(expf(-fabsf(xs)));
        float sg = fmaxf(sp, 1e-4f);
        g_mu[row] = m_;
        float inv0 = rsqrtf(sg + 2.5e-5f);
        float inv1 = rsqrtf(sg + 1.0e-4f);
        g_amp[0][row] = inv0 * INV_SQRT_2PI;
        g_amp[1][row] = inv1 * INV_SQRT_2PI;
        g_c2[0][row]  = NHALF_LOG2E * inv0 * inv0;
        g_c2[1][row]  = NHALF_LOG2E * inv1 * inv1;
    }
}

// ----------------------------------------------------------------------------
// launch
// ----------------------------------------------------------------------------
extern "C" void kernel_launch(void* const* d_in, const int* in_sizes, int n_in,
                              void* d_out, int out_size) {
    (void)in_sizes; (void)n_in; (void)out_size;
    const float* k_in = (const float*)d_in[0];
    const float* q_in = (const float*)d_in[1];
    const float* Wk   = (const float*)d_in[2];
    const float* Wv   = (const float*)d_in[3];
    const float* Wo   = (const float*)d_in[4];
    const float* wmu  = (const float*)d_in[5];
    const float* wsig = (const float*)d_in[6];

    compute_G_host();
    cudaMemcpyToSymbolAsync(g_GTh, hostGTh, sizeof(hostGTh), 0, cudaMemcpyHostToDevice, 0);
    cudaMemcpyToSymbolAsync(g_GTl, hostGTl, sizeof(hostGTl), 0, cudaMemcpyHostToDevice, 0);
    cudaMemcpyToSymbolAsync(g_bmu, hostbmu, sizeof(hostbmu), 0, cudaMemcpyHostToDevice, 0);

    __nv_bfloat16 *pGTh, *pGTl, *pkh, *pkl, *pWvh, *pWvl, *pWoh, *pWol;
    __nv_bfloat16 *pPvh, *pPvl, *pVh, *pVl, *pCh, *pCl;
    cudaGetSymbolAddress((void**)&pGTh, g_GTh); cudaGetSymbolAddress((void**)&pGTl, g_GTl);
    cudaGetSymbolAddress((void**)&pkh,  g_kh);  cudaGetSymbolAddress((void**)&pkl,  g_kl);
    cudaGetSymbolAddress((void**)&pWvh, g_Wvh); cudaGetSymbolAddress((void**)&pWvl, g_Wvl);
    cudaGetSymbolAddress((void**)&pWoh, g_Woh); cudaGetSymbolAddress((void**)&pWol, g_Wol);
    cudaGetSymbolAddress((void**)&pPvh, g_Pvh); cudaGetSymbolAddress((void**)&pPvl, g_Pvl);
    cudaGetSymbolAddress((void**)&pVh,  g_Vh);  cudaGetSymbolAddress((void**)&pVl,  g_Vl);
    cudaGetSymbolAddress((void**)&pCh,  g_Ch);  cudaGetSymbolAddress((void**)&pCl,  g_Cl);

    cudaFuncSetAttribute(gemm_mma_nt,
                         cudaFuncAttributeMaxDynamicSharedMemorySize, GSMEM_B);
    cudaFuncSetAttribute(ctx_mma,
                         cudaFuncAttributeMaxDynamicSharedMemorySize, CSMEM_B);

    const int n4W = DM * DM / 4, n4k = MEM * DM / 4;

    // splits
    split_kernel<<<(n4k + 255) / 256, 256>>>((const float4*)k_in,
        (__nv_bfloat162*)pkh, (__nv_bfloat162*)pkl, n4k);
    split_kernel<<<(n4W + 255) / 256, 256>>>((const float4*)Wv,
        (__nv_bfloat162*)pWvh, (__nv_bfloat162*)pWvl, n4W);
    split_kernel<<<(n4W + 255) / 256, 256>>>((const float4*)Wo,
        (__nv_bfloat162*)pWoh, (__nv_bfloat162*)pWol, n4W);

    // Pv^T[hd][l] = Wv . k^T   (NT: A=Wv[hd][e], B=k[l][e]), K=2048
    gemm_mma_nt<<<dim3(DM / 128, MEM / 128), 256, GSMEM_B>>>(
        pWvh, pWvl, pkh, pkl, nullptr, pPvh, pPvl, MEM, DM, 1.0f);
    // V^T[hd][n] = Pv^T . G    (NT: A=Pv^T[hd][l], B=G^T[n][l]), K=512
    gemm_mma_nt<<<dim3(DM / 128, NB / 128), 256, GSMEM_B>>>(
        pPvh, pPvl, pGTh, pGTl, nullptr, pVh, pVl, NB, MEM, 1.0f);

    // km/ks: gw = G.w (over bf16 G), bv = k^T.gw, km = Wk.bv / sqrt(D)
    gw_kernel<<<MEM / 128, 128>>>(wmu, wsig);
    bv_part<<<dim3(DM / 256, 4), 256>>>(k_in);
    bv_reduce<<<DM / 256, 256>>>();
    kmdot_kernel<<<DM / 8, 256>>>(Wk);
    musig_kernel<<<(H_ * QL) / 8, 256>>>(q_in);

    // ctx on tensor cores (writes Ch/Cl directly)
    ctx_mma<<<dim3(QL / 128, H_), 256, CSMEM_B>>>();

    // out = ctx . Wo^T  (fp32 output)
    gemm_mma_nt<<<dim3(QL / 128, DM / 128), 256, GSMEM_B>>>(
        pCh, pCl, pWoh, pWol, (float*)d_out, nullptr, nullptr, DM, DM, 1.0f);
}